// round 7
// baseline (speedup 1.0000x reference)
#include <cuda_runtime.h>
#include <cuda_fp16.h>
#include <math.h>
#include <stdint.h>

#define B_ 512
#define T_ 256
#define E_ 384
#define H_ 64
#define M_ (B_ * T_)   // 131072

// Projected q,k,v stored as fp16 (16.8 MB each)
__device__ __half g_q[(size_t)M_ * H_];
__device__ __half g_k[(size_t)M_ * H_];
__device__ __half g_v[(size_t)M_ * H_];
__device__ __half g_wh[192 * 384];   // W^T as fp16: [n][k], n = m*64+h

__device__ __forceinline__ unsigned pack_h2(float lo, float hi) {
    unsigned d;
    asm("cvt.rn.f16x2.f32 %0, %1, %2;" : "=r"(d) : "f"(hi), "f"(lo));
    return d;
}
__device__ __forceinline__ void cpa16(uint32_t dst, const void* src) {
    asm volatile("cp.async.cg.shared.global [%0], [%1], 16;"
                 :: "r"(dst), "l"(src) : "memory");
}
__device__ __forceinline__ uint32_t s2u(const void* p) {
    uint32_t a;
    asm("{ .reg .u64 t; cvta.to.shared.u64 t, %1; cvt.u32.u64 %0, t; }"
        : "=r"(a) : "l"(p));
    return a;
}

#define MMA_F16(C, A, B0, B1)                                               \
    asm volatile(                                                           \
        "mma.sync.aligned.m16n8k16.row.col.f32.f16.f16.f32 "                \
        "{%0,%1,%2,%3}, {%4,%5,%6,%7}, {%8,%9}, {%0,%1,%2,%3};"             \
        : "+f"((C)[0]), "+f"((C)[1]), "+f"((C)[2]), "+f"((C)[3])            \
        : "r"((A)[0]), "r"((A)[1]), "r"((A)[2]), "r"((A)[3]),               \
          "r"(B0), "r"(B1))

// ---------------------------------------------------------------------------
// Kernel 0: W -> fp16, layout g_wh[n][k]  (n = m*64 + h, k = 0..383)
// ---------------------------------------------------------------------------
__global__ __launch_bounds__(256) void wh_kernel(
    const float* __restrict__ Wq, const float* __restrict__ Wk,
    const float* __restrict__ Wv)
{
    int idx = blockIdx.x * 256 + threadIdx.x;   // 0..73727
    int n = idx / 384, k = idx % 384;
    const float* Wm = (n < 64) ? Wq : ((n < 128) ? Wk : Wv);
    g_wh[idx] = __float2half_rn(Wm[(size_t)k * 64 + (n & 63)]);
}

// ---------------------------------------------------------------------------
// Kernel 1: fused QKV projection, fp16 mma m16n8k16, cp.async double buffer.
// CTA: 128 rows x 192 cols. 512 threads, 16 warps, warp tile 32x48.
// smem: Xs fp32 [2][128][36] | Wh half [2][192][40]
// x staged fp32, packed to half at fragment-read (cvt.rn.f16x2.f32).
// ---------------------------------------------------------------------------
#define XT_STRIDE 36                   // floats
#define WH_STRIDE 40                   // halfs (20 uints): conflict-free 20g+t
#define XS_FLOATS (128 * XT_STRIDE)    // 4608 per stage
#define WS_UINTS  (192 * WH_STRIDE / 2) // 3840 per stage
#define WBASE_U   (2 * XS_FLOATS)      // uint offset of W stage 0
#define QKV_SMEM_BYTES ((2 * XS_FLOATS + 2 * WS_UINTS) * 4)   // 67584

__global__ __launch_bounds__(512, 1) void qkv_fp16_kernel(const float* __restrict__ x)
{
    extern __shared__ __align__(16) unsigned sm[];
    const uint32_t sb = s2u(sm);
    const int tid  = threadIdx.x;
    const int warp = tid >> 5;
    const int lane = tid & 31;
    const int g    = lane >> 2;
    const int t    = lane & 3;
    const int row0 = blockIdx.x * 128;

    const int mbase = (warp >> 2) * 32;   // 0,32,64,96
    const int nbase = (warp & 3) * 48;    // 0,48,96,144

    const float* xp = x + (size_t)row0 * E_;

    auto prefetch = [&](int s, int kb) {
        const uint32_t xbase = sb + (s * XS_FLOATS) * 4;
        #pragma unroll
        for (int i = 0; i < 2; i++) {                  // 1024 x 16B
            int f = tid + i * 512;
            int r = f >> 3, c4 = f & 7;
            cpa16(xbase + (r * XT_STRIDE + c4 * 4) * 4,
                  xp + (size_t)r * E_ + kb * 32 + c4 * 4);
        }
        const uint32_t wbase = sb + (WBASE_U + s * WS_UINTS) * 4;
        #pragma unroll
        for (int i = 0; i < 2; i++) {                  // 768 x 16B
            int f = tid + i * 512;
            if (f < 768) {
                int n = f >> 2, c = f & 3;             // 8 halfs per 16B
                cpa16(wbase + (n * WH_STRIDE + c * 8) * 2,
                      g_wh + (size_t)n * 384 + kb * 32 + c * 8);
            }
        }
        asm volatile("cp.async.commit_group;" ::: "memory");
    };

    float c[2][6][4] = {};

    prefetch(0, 0);

    for (int kb = 0; kb < 12; kb++) {
        const int s = kb & 1;
        if (kb + 1 < 12) {
            prefetch(s ^ 1, kb + 1);
            asm volatile("cp.async.wait_group 1;" ::: "memory");
        } else {
            asm volatile("cp.async.wait_group 0;" ::: "memory");
        }
        __syncthreads();

        const float*    Xsf = (const float*)(sm + s * XS_FLOATS);
        const unsigned* Whu = sm + WBASE_U + s * WS_UINTS;

        #pragma unroll
        for (int kk = 0; kk < 32; kk += 16) {
            unsigned a[2][4];
            #pragma unroll
            for (int mt = 0; mt < 2; mt++) {
                int r = mbase + mt * 16 + g;
                float2 x00 = *(const float2*)(Xsf + r * XT_STRIDE + kk + 2 * t);
                float2 x10 = *(const float2*)(Xsf + (r + 8) * XT_STRIDE + kk + 2 * t);
                float2 x01 = *(const float2*)(Xsf + r * XT_STRIDE + kk + 2 * t + 8);
                float2 x11 = *(const float2*)(Xsf + (r + 8) * XT_STRIDE + kk + 2 * t + 8);
                a[mt][0] = pack_h2(x00.x, x00.y);
                a[mt][1] = pack_h2(x10.x, x10.y);
                a[mt][2] = pack_h2(x01.x, x01.y);
                a[mt][3] = pack_h2(x11.x, x11.y);
            }
            #pragma unroll
            for (int nt = 0; nt < 6; nt++) {
                int col = nbase + nt * 8 + g;
                unsigned b0 = Whu[col * 20 + (kk >> 1) + t];
                unsigned b1 = Whu[col * 20 + (kk >> 1) + t + 4];
                #pragma unroll
                for (int mt = 0; mt < 2; mt++)
                    MMA_F16(c[mt][nt], a[mt], b0, b1);
            }
        }
        __syncthreads();
    }

    // Epilogue: pack fp32 accum -> half2, store to g_q/g_k/g_v
    #pragma unroll
    for (int mt = 0; mt < 2; mt++) {
        #pragma unroll
        for (int nt = 0; nt < 6; nt++) {
            int col = nbase + nt * 8 + 2 * t;
            int m = col >> 6;
            int h = col & 63;
            __half* o = (m == 0) ? g_q : ((m == 1) ? g_k : g_v);
            int r = row0 + mbase + mt * 16 + g;
            *(unsigned*)&o[(size_t)r * H_ + h]       = pack_h2(c[mt][nt][0], c[mt][nt][1]);
            *(unsigned*)&o[(size_t)(r + 8) * H_ + h] = pack_h2(c[mt][nt][2], c[mt][nt][3]);
        }
    }
}

// ---------------------------------------------------------------------------
// Kernel 2: flash attention, fp16 mma m16n8k16.
// grid (T/128, B), 256 threads, 8 warps, warp owns 16 q-rows.
// smem halfs (stride 72): Ks[64][72] | Vs[64][72] ([h][c]) | Ps/Qs[128][72]
// ---------------------------------------------------------------------------
#define ASTR   72                       // halfs; uint stride 36 -> banks 4g+t
#define KS_OFF 0
#define VS_OFF (64 * ASTR)
#define PS_OFF (128 * ASTR)
#define ATTN_SMEM_BYTES ((256 * ASTR) * 2)   // 36864

__global__ __launch_bounds__(256, 2) void attn_fp16_kernel(float* __restrict__ out)
{
    extern __shared__ __align__(16) __half smh[];
    __half* Ks = smh + KS_OFF;
    __half* Vs = smh + VS_OFF;
    __half* Ps = smh + PS_OFF;
    unsigned* Ku = (unsigned*)Ks;
    unsigned* Vu = (unsigned*)Vs;
    unsigned* Pu = (unsigned*)Ps;

    const int tid  = threadIdx.x;
    const int warp = tid >> 5;
    const int lane = tid & 31;
    const int g    = lane >> 2;
    const int t    = lane & 3;
    const int q0   = blockIdx.x * 128;
    const int b    = blockIdx.y;

    // --- Stage Q (scale by 0.125, exact in fp16) into Ps region ---
    const __half* qp = g_q + ((size_t)b * T_ + q0) * H_;
    const __half2 sc = __float2half2_rn(0.125f);
    #pragma unroll
    for (int i = 0; i < 4; i++) {
        int f = tid + i * 256;            // 1024
        int r = f >> 3, h8 = (f & 7) * 8;
        uint4 v = *(const uint4*)(qp + (size_t)r * 64 + h8);
        __half2* hv = (__half2*)&v;
        hv[0] = __hmul2(hv[0], sc); hv[1] = __hmul2(hv[1], sc);
        hv[2] = __hmul2(hv[2], sc); hv[3] = __hmul2(hv[3], sc);
        *(uint4*)(Ps + r * ASTR + h8) = v;
    }
    __syncthreads();

    // --- Q fragments (4 k-steps over H=64) ---
    const int lr = warp * 16 + g;
    unsigned qf[4][4];
    #pragma unroll
    for (int s = 0; s < 4; s++) {
        qf[s][0] = Pu[lr * 36 + 8 * s + t];
        qf[s][1] = Pu[(lr + 8) * 36 + 8 * s + t];
        qf[s][2] = Pu[lr * 36 + 8 * s + t + 4];
        qf[s][3] = Pu[(lr + 8) * 36 + 8 * s + t + 4];
    }

    float o[8][4] = {};
    float m0 = -1e30f, m1 = -1e30f, l0 = 0.0f, l1 = 0.0f;

    const int row_min = q0 + warp * 16;
    const int row_max = row_min + 15;
    const int r0g = row_min + g;
    const int ktmax = (q0 + 127) >> 6;

    const __half* kp = g_k + (size_t)b * T_ * H_;
    const __half* vp = g_v + (size_t)b * T_ * H_;

    for (int kt = 0; kt <= ktmax; kt++) {
        // K tile: direct uint4 copy, Ks[c][h]
        #pragma unroll
        for (int i = 0; i < 2; i++) {
            int f = tid + i * 256;        // 512
            int c = f >> 3, h8 = (f & 7) * 8;
            uint4 v = *(const uint4*)(kp + (size_t)(kt * 64 + c) * 64 + h8);
            *(uint4*)(Ks + c * ASTR + h8) = v;
        }
        // V tile: transpose to Vs[h][c] (half scatter)
        #pragma unroll
        for (int i = 0; i < 2; i++) {
            int f = tid + i * 256;
            int c = f >> 3, h8 = (f & 7) * 8;
            uint4 v = *(const uint4*)(vp + (size_t)(kt * 64 + c) * 64 + h8);
            const __half* hv = (const __half*)&v;
            #pragma unroll
            for (int j = 0; j < 8; j++)
                Vs[(h8 + j) * ASTR + c] = hv[j];
        }
        __syncthreads();

        if (kt * 64 <= row_max) {   // warp-uniform skip of fully-masked tiles
            // S = Q K^T
            float s[8][4] = {};
            #pragma unroll
            for (int nt = 0; nt < 8; nt++) {
                int cc = nt * 8 + g;
                #pragma unroll
                for (int ks = 0; ks < 4; ks++) {
                    unsigned b0 = Ku[cc * 36 + 8 * ks + t];
                    unsigned b1 = Ku[cc * 36 + 8 * ks + t + 4];
                    MMA_F16(s[nt], qf[ks], b0, b1);
                }
            }

            // Causal mask
            if (kt * 64 + 63 > row_min) {
                int colb = kt * 64 + 2 * t;
                #pragma unroll
                for (int nt = 0; nt < 8; nt++) {
                    int c0 = colb + nt * 8, c1 = c0 + 1;
                    if (c0 > r0g)     s[nt][0] = -1e30f;
                    if (c1 > r0g)     s[nt][1] = -1e30f;
                    if (c0 > r0g + 8) s[nt][2] = -1e30f;
                    if (c1 > r0g + 8) s[nt][3] = -1e30f;
                }
            }

            // Online softmax (rows lr, lr+8; quad reduction)
            float mx0 = -1e30f, mx1 = -1e30f;
            #pragma unroll
            for (int nt = 0; nt < 8; nt++) {
                mx0 = fmaxf(mx0, fmaxf(s[nt][0], s[nt][1]));
                mx1 = fmaxf(mx1, fmaxf(s[nt][2], s[nt][3]));
            }
            mx0 = fmaxf(mx0, __shfl_xor_sync(0xffffffffu, mx0, 1));
            mx0 = fmaxf(mx0, __shfl_xor_sync(0xffffffffu, mx0, 2));
            mx1 = fmaxf(mx1, __shfl_xor_sync(0xffffffffu, mx1, 1));
            mx1 = fmaxf(mx1, __shfl_xor_sync(0xffffffffu, mx1, 2));

            float mn0 = fmaxf(m0, mx0), mn1 = fmaxf(m1, mx1);
            float cr0 = __expf(m0 - mn0), cr1 = __expf(m1 - mn1);
            float sum0 = 0.0f, sum1 = 0.0f;
            #pragma unroll
            for (int nt = 0; nt < 8; nt++) {
                s[nt][0] = __expf(s[nt][0] - mn0);
                s[nt][1] = __expf(s[nt][1] - mn0);
                s[nt][2] = __expf(s[nt][2] - mn1);
                s[nt][3] = __expf(s[nt][3] - mn1);
                sum0 += s[nt][0] + s[nt][1];
                sum1 += s[nt][2] + s[nt][3];
            }
            sum0 += __shfl_xor_sync(0xffffffffu, sum0, 1);
            sum0 += __shfl_xor_sync(0xffffffffu, sum0, 2);
            sum1 += __shfl_xor_sync(0xffffffffu, sum1, 1);
            sum1 += __shfl_xor_sync(0xffffffffu, sum1, 2);

            l0 = l0 * cr0 + sum0;  l1 = l1 * cr1 + sum1;
            m0 = mn0;              m1 = mn1;
            #pragma unroll
            for (int nt = 0; nt < 8; nt++) {
                o[nt][0] *= cr0; o[nt][1] *= cr0;
                o[nt][2] *= cr1; o[nt][3] *= cr1;
            }

            // P -> smem as half2
            #pragma unroll
            for (int nt = 0; nt < 8; nt++) {
                Pu[lr * 36 + nt * 4 + t]       = pack_h2(s[nt][0], s[nt][1]);
                Pu[(lr + 8) * 36 + nt * 4 + t] = pack_h2(s[nt][2], s[nt][3]);
            }
            __syncwarp();

            unsigned af[4][4];
            #pragma unroll
            for (int ks = 0; ks < 4; ks++) {
                af[ks][0] = Pu[lr * 36 + 8 * ks + t];
                af[ks][1] = Pu[(lr + 8) * 36 + 8 * ks + t];
                af[ks][2] = Pu[lr * 36 + 8 * ks + t + 4];
                af[ks][3] = Pu[(lr + 8) * 36 + 8 * ks + t + 4];
            }

            // O += P V
            #pragma unroll
            for (int nt = 0; nt < 8; nt++) {
                int col = nt * 8 + g;
                #pragma unroll
                for (int ks = 0; ks < 4; ks++) {
                    unsigned b0 = Vu[col * 36 + 8 * ks + t];
                    unsigned b1 = Vu[col * 36 + 8 * ks + t + 4];
                    MMA_F16(o[nt], af[ks], b0, b1);
                }
            }
        }
        __syncthreads();
    }

    float inv0 = 1.0f / l0, inv1 = 1.0f / l1;
    float* op0 = out + ((size_t)b * T_ + q0 + lr) * 64;
    float* op1 = out + ((size_t)b * T_ + q0 + lr + 8) * 64;
    #pragma unroll
    for (int nt = 0; nt < 8; nt++) {
        int col = nt * 8 + 2 * t;
        *(float2*)&op0[col] = make_float2(o[nt][0] * inv0, o[nt][1] * inv0);
        *(float2*)&op1[col] = make_float2(o[nt][2] * inv1, o[nt][3] * inv1);
    }
}

// ---------------------------------------------------------------------------
extern "C" void kernel_launch(void* const* d_in, const int* in_sizes, int n_in,
                              void* d_out, int out_size)
{
    const float* x  = (const float*)d_in[0];
    const float* Wq = (const float*)d_in[1];
    const float* Wk = (const float*)d_in[2];
    const float* Wv = (const float*)d_in[3];
    float* out = (float*)d_out;

    wh_kernel<<<288, 256>>>(Wq, Wk, Wv);

    cudaFuncSetAttribute(qkv_fp16_kernel,
                         cudaFuncAttributeMaxDynamicSharedMemorySize,
                         QKV_SMEM_BYTES);
    qkv_fp16_kernel<<<M_ / 128, 512, QKV_SMEM_BYTES>>>(x);

    cudaFuncSetAttribute(attn_fp16_kernel,
                         cudaFuncAttributeMaxDynamicSharedMemorySize,
                         ATTN_SMEM_BYTES);
    attn_fp16_kernel<<<dim3(T_ / 128, B_), 256, ATTN_SMEM_BYTES>>>(out);
}

// round 8
// speedup vs baseline: 1.5271x; 1.5271x over previous
#include <cuda_runtime.h>
#include <cuda_fp16.h>
#include <math.h>
#include <stdint.h>

#define B_ 512
#define T_ 256
#define E_ 384
#define H_ 64
#define M_ (B_ * T_)   // 131072

// Projected q,k,v stored as fp16
__device__ __half g_q[(size_t)M_ * H_];
__device__ __half g_k[(size_t)M_ * H_];
__device__ __half g_v[(size_t)M_ * H_];
__device__ unsigned g_wt[384 * 192];   // W tf32 [k][n], n = m*64+h

__device__ __forceinline__ unsigned f2tf32(float f) {
    unsigned u;
    asm("cvt.rna.tf32.f32 %0, %1;" : "=r"(u) : "f"(f));
    return u;
}
__device__ __forceinline__ unsigned u2tf32(unsigned x) {
    unsigned u;
    asm("cvt.rna.tf32.f32 %0, %1;" : "=r"(u) : "f"(__uint_as_float(x)));
    return u;
}
__device__ __forceinline__ unsigned pack_h2(float lo, float hi) {
    unsigned d;
    asm("cvt.rn.f16x2.f32 %0, %1, %2;" : "=r"(d) : "f"(hi), "f"(lo));
    return d;
}
__device__ __forceinline__ uint32_t s2u(const void* p) {
    uint32_t a;
    asm("{ .reg .u64 t; cvta.to.shared.u64 t, %1; cvt.u32.u64 %0, t; }"
        : "=r"(a) : "l"(p));
    return a;
}
__device__ __forceinline__ void cpa16(uint32_t dst, const void* src) {
    asm volatile("cp.async.cg.shared.global [%0], [%1], 16;"
                 :: "r"(dst), "l"(src) : "memory");
}

#define MMA_TF32(C, A, B0, B1)                                              \
    asm volatile(                                                           \
        "mma.sync.aligned.m16n8k8.row.col.f32.tf32.tf32.f32 "               \
        "{%0,%1,%2,%3}, {%4,%5,%6,%7}, {%8,%9}, {%0,%1,%2,%3};"             \
        : "+f"((C)[0]), "+f"((C)[1]), "+f"((C)[2]), "+f"((C)[3])            \
        : "r"((A)[0]), "r"((A)[1]), "r"((A)[2]), "r"((A)[3]),               \
          "r"(B0), "r"(B1))

#define MMA_F16(C, A, B0, B1)                                               \
    asm volatile(                                                           \
        "mma.sync.aligned.m16n8k16.row.col.f32.f16.f16.f32 "                \
        "{%0,%1,%2,%3}, {%4,%5,%6,%7}, {%8,%9}, {%0,%1,%2,%3};"             \
        : "+f"((C)[0]), "+f"((C)[1]), "+f"((C)[2]), "+f"((C)[3])            \
        : "r"((A)[0]), "r"((A)[1]), "r"((A)[2]), "r"((A)[3]),               \
          "r"(B0), "r"(B1))

#define LDM_X4(R0, R1, R2, R3, ADDR)                                        \
    asm volatile("ldmatrix.sync.aligned.m8n8.x4.shared.b16 "                \
                 "{%0,%1,%2,%3}, [%4];"                                     \
                 : "=r"(R0), "=r"(R1), "=r"(R2), "=r"(R3) : "r"(ADDR))

#define LDM_X4_T(R0, R1, R2, R3, ADDR)                                      \
    asm volatile("ldmatrix.sync.aligned.m8n8.x4.trans.shared.b16 "          \
                 "{%0,%1,%2,%3}, [%4];"                                     \
                 : "=r"(R0), "=r"(R1), "=r"(R2), "=r"(R3) : "r"(ADDR))

// ---------------------------------------------------------------------------
// Kernel 0: W -> tf32, interleaved layout g_wt[k][n], n = m*64 + h
// ---------------------------------------------------------------------------
__global__ __launch_bounds__(256) void wt_kernel(
    const float* __restrict__ Wq, const float* __restrict__ Wk,
    const float* __restrict__ Wv)
{
    int idx = blockIdx.x * 256 + threadIdx.x;
    int k = idx / 192, n = idx % 192;
    const float* Wm = (n < 64) ? Wq : ((n < 128) ? Wk : Wv);
    g_wt[idx] = f2tf32(Wm[(size_t)k * 64 + (n & 63)]);
}

// ---------------------------------------------------------------------------
// Kernel 1: fused QKV projection — R6 tf32 pipeline, fp16 output.
// CTA 128x192, 512 threads, cp.async double buffer.
// ---------------------------------------------------------------------------
#define XT_STRIDE 36
#define WT_STRIDE 200
#define XS_FLOATS (128 * XT_STRIDE)
#define WS_FLOATS (32 * WT_STRIDE)
#define WS_BASE   (2 * XS_FLOATS)
#define QKV_SMEM_BYTES ((2 * XS_FLOATS + 2 * WS_FLOATS) * 4)   // 88064

__global__ __launch_bounds__(512, 1) void qkv_tc2_kernel(const float* __restrict__ x)
{
    extern __shared__ __align__(16) unsigned sm[];
    const uint32_t sb = s2u(sm);
    const int tid  = threadIdx.x;
    const int warp = tid >> 5;
    const int lane = tid & 31;
    const int row0 = blockIdx.x * 128;

    const int mbase = (warp >> 2) * 32;
    const int nbase = (warp & 3) * 48;

    const float* xp = x + (size_t)row0 * E_;

    auto prefetch = [&](int s, int kb) {
        const uint32_t xbase = sb + (s * XS_FLOATS) * 4;
        #pragma unroll
        for (int i = 0; i < 2; i++) {
            int f = tid + i * 512;
            int r = f >> 3, c4 = f & 7;
            cpa16(xbase + (r * XT_STRIDE + c4 * 4) * 4,
                  xp + (size_t)r * E_ + kb * 32 + c4 * 4);
        }
        const uint32_t wbase = sb + (WS_BASE + s * WS_FLOATS) * 4;
        #pragma unroll
        for (int i = 0; i < 3; i++) {
            int f = tid + i * 512;
            int r = f / 48, c4 = f % 48;
            cpa16(wbase + (r * WT_STRIDE + c4 * 4) * 4,
                  g_wt + (size_t)(kb * 32 + r) * 192 + c4 * 4);
        }
        asm volatile("cp.async.commit_group;" ::: "memory");
    };

    float c[2][6][4] = {};

    prefetch(0, 0);

    for (int kb = 0; kb < 12; kb++) {
        const int s = kb & 1;
        if (kb + 1 < 12) {
            prefetch(s ^ 1, kb + 1);
            asm volatile("cp.async.wait_group 1;" ::: "memory");
        } else {
            asm volatile("cp.async.wait_group 0;" ::: "memory");
        }
        __syncthreads();

        const unsigned* Xs = sm + s * XS_FLOATS;
        const unsigned* Ws = sm + WS_BASE + s * WS_FLOATS;

        #pragma unroll
        for (int kk = 0; kk < 32; kk += 8) {
            unsigned a[2][4];
            #pragma unroll
            for (int mt = 0; mt < 2; mt++) {
                int r  = mbase + mt * 16 + (lane >> 2);
                int cc = kk + (lane & 3);
                a[mt][0] = u2tf32(Xs[r * XT_STRIDE + cc]);
                a[mt][1] = u2tf32(Xs[(r + 8) * XT_STRIDE + cc]);
                a[mt][2] = u2tf32(Xs[r * XT_STRIDE + cc + 4]);
                a[mt][3] = u2tf32(Xs[(r + 8) * XT_STRIDE + cc + 4]);
            }
            #pragma unroll
            for (int nt = 0; nt < 6; nt++) {
                int col = nbase + nt * 8 + (lane >> 2);
                int rr  = kk + (lane & 3);
                unsigned b0 = Ws[rr * WT_STRIDE + col];
                unsigned b1 = Ws[(rr + 4) * WT_STRIDE + col];
                #pragma unroll
                for (int mt = 0; mt < 2; mt++)
                    MMA_TF32(c[mt][nt], a[mt], b0, b1);
            }
        }
        __syncthreads();
    }

    // Epilogue: pack fp32 accum -> fp16
    #pragma unroll
    for (int mt = 0; mt < 2; mt++) {
        #pragma unroll
        for (int nt = 0; nt < 6; nt++) {
            int col = nbase + nt * 8 + (lane & 3) * 2;
            int m = col >> 6;
            int h = col & 63;
            __half* o = (m == 0) ? g_q : ((m == 1) ? g_k : g_v);
            int r = row0 + mbase + mt * 16 + (lane >> 2);
            *(unsigned*)&o[(size_t)r * H_ + h]       = pack_h2(c[mt][nt][0], c[mt][nt][1]);
            *(unsigned*)&o[(size_t)(r + 8) * H_ + h] = pack_h2(c[mt][nt][2], c[mt][nt][3]);
        }
    }
}

// ---------------------------------------------------------------------------
// Kernel 2: flash attention, fp16 mma + ldmatrix + register P-repack.
// grid (T/128, B), 256 threads, 8 warps, warp owns 16 q-rows.
// smem halfs: Ks[64][72] | Vs[64][72] (both row-major [c][h]) | Qs[128][72]
// ---------------------------------------------------------------------------
#define ASTR   72
#define KS_OFF 0
#define VS_OFF (64 * ASTR)
#define QS_OFF (128 * ASTR)
#define ATTN_SMEM_BYTES ((256 * ASTR) * 2)   // 36864

__global__ __launch_bounds__(256, 2) void attn_fp16_kernel(float* __restrict__ out)
{
    extern __shared__ __align__(16) __half smh[];
    const uint32_t sb = s2u(smh);
    __half* Ks = smh + KS_OFF;
    __half* Vs = smh + VS_OFF;
    __half* Qs = smh + QS_OFF;
    unsigned* Qu = (unsigned*)Qs;

    const int tid  = threadIdx.x;
    const int warp = tid >> 5;
    const int lane = tid & 31;
    const int g    = lane >> 2;
    const int t    = lane & 3;
    const int q0   = blockIdx.x * 128;
    const int b    = blockIdx.y;

    // --- Stage Q (scaled by 0.125) ---
    const __half* qp = g_q + ((size_t)b * T_ + q0) * H_;
    const __half2 sc = __float2half2_rn(0.125f);
    #pragma unroll
    for (int i = 0; i < 4; i++) {
        int f = tid + i * 256;
        int r = f >> 3, h8 = (f & 7) * 8;
        uint4 v = *(const uint4*)(qp + (size_t)r * 64 + h8);
        __half2* hv = (__half2*)&v;
        hv[0] = __hmul2(hv[0], sc); hv[1] = __hmul2(hv[1], sc);
        hv[2] = __hmul2(hv[2], sc); hv[3] = __hmul2(hv[3], sc);
        *(uint4*)(Qs + r * ASTR + h8) = v;
    }
    __syncthreads();

    // --- Q fragments ---
    const int lr = warp * 16 + g;
    unsigned qf[4][4];
    #pragma unroll
    for (int s = 0; s < 4; s++) {
        qf[s][0] = Qu[lr * 36 + 8 * s + t];
        qf[s][1] = Qu[(lr + 8) * 36 + 8 * s + t];
        qf[s][2] = Qu[lr * 36 + 8 * s + t + 4];
        qf[s][3] = Qu[(lr + 8) * 36 + 8 * s + t + 4];
    }

    float o[8][4] = {};
    float m0 = -1e30f, m1 = -1e30f, l0 = 0.0f, l1 = 0.0f;

    const int row_min = q0 + warp * 16;
    const int row_max = row_min + 15;
    const int r0g = row_min + g;
    const int ktmax = (q0 + 127) >> 6;

    const __half* kp = g_k + (size_t)b * T_ * H_;
    const __half* vp = g_v + (size_t)b * T_ * H_;

    // ldmatrix lane-role constants
    const int lrow = lane & 7;          // row within 8x8 matrix
    const int lmat = lane >> 3;         // which matrix (0..3)

    for (int kt = 0; kt <= ktmax; kt++) {
        // K and V tiles: row-major [c][h], uint4 copies (conflict-free)
        #pragma unroll
        for (int i = 0; i < 2; i++) {
            int f = tid + i * 256;
            int c = f >> 3, h8 = (f & 7) * 8;
            *(uint4*)(Ks + c * ASTR + h8) =
                *(const uint4*)(kp + (size_t)(kt * 64 + c) * 64 + h8);
            *(uint4*)(Vs + c * ASTR + h8) =
                *(const uint4*)(vp + (size_t)(kt * 64 + c) * 64 + h8);
        }
        __syncthreads();

        if (kt * 64 <= row_max) {
            // --- S = Q K^T ---
            float s[8][4] = {};
            #pragma unroll
            for (int nt = 0; nt < 8; nt++) {
                #pragma unroll
                for (int jj = 0; jj < 2; jj++) {
                    // matrices: h blocks [32jj+8*lmat, +8) on row c = nt*8+lrow
                    uint32_t addr = sb + 2 * (KS_OFF + (nt * 8 + lrow) * ASTR
                                              + 32 * jj + 8 * lmat);
                    unsigned r0, r1, r2, r3;
                    LDM_X4(r0, r1, r2, r3, addr);
                    MMA_F16(s[nt], qf[2 * jj],     r0, r1);
                    MMA_F16(s[nt], qf[2 * jj + 1], r2, r3);
                }
            }

            // --- causal mask ---
            if (kt * 64 + 63 > row_min) {
                int colb = kt * 64 + 2 * t;
                #pragma unroll
                for (int nt = 0; nt < 8; nt++) {
                    int c0 = colb + nt * 8, c1 = c0 + 1;
                    if (c0 > r0g)     s[nt][0] = -1e30f;
                    if (c1 > r0g)     s[nt][1] = -1e30f;
                    if (c0 > r0g + 8) s[nt][2] = -1e30f;
                    if (c1 > r0g + 8) s[nt][3] = -1e30f;
                }
            }

            // --- online softmax (rows lr, lr+8) ---
            float mx0 = -1e30f, mx1 = -1e30f;
            #pragma unroll
            for (int nt = 0; nt < 8; nt++) {
                mx0 = fmaxf(mx0, fmaxf(s[nt][0], s[nt][1]));
                mx1 = fmaxf(mx1, fmaxf(s[nt][2], s[nt][3]));
            }
            mx0 = fmaxf(mx0, __shfl_xor_sync(0xffffffffu, mx0, 1));
            mx0 = fmaxf(mx0, __shfl_xor_sync(0xffffffffu, mx0, 2));
            mx1 = fmaxf(mx1, __shfl_xor_sync(0xffffffffu, mx1, 1));
            mx1 = fmaxf(mx1, __shfl_xor_sync(0xffffffffu, mx1, 2));

            float mn0 = fmaxf(m0, mx0), mn1 = fmaxf(m1, mx1);
            float cr0 = __expf(m0 - mn0), cr1 = __expf(m1 - mn1);
            float sum0 = 0.0f, sum1 = 0.0f;
            #pragma unroll
            for (int nt = 0; nt < 8; nt++) {
                s[nt][0] = __expf(s[nt][0] - mn0);
                s[nt][1] = __expf(s[nt][1] - mn0);
                s[nt][2] = __expf(s[nt][2] - mn1);
                s[nt][3] = __expf(s[nt][3] - mn1);
                sum0 += s[nt][0] + s[nt][1];
                sum1 += s[nt][2] + s[nt][3];
            }
            sum0 += __shfl_xor_sync(0xffffffffu, sum0, 1);
            sum0 += __shfl_xor_sync(0xffffffffu, sum0, 2);
            sum1 += __shfl_xor_sync(0xffffffffu, sum1, 1);
            sum1 += __shfl_xor_sync(0xffffffffu, sum1, 2);

            l0 = l0 * cr0 + sum0;  l1 = l1 * cr1 + sum1;
            m0 = mn0;              m1 = mn1;
            #pragma unroll
            for (int nt = 0; nt < 8; nt++) {
                o[nt][0] *= cr0; o[nt][1] *= cr0;
                o[nt][2] *= cr1; o[nt][3] *= cr1;
            }

            // --- P repack: S accum layout -> A fragment, in registers ---
            unsigned af[4][4];
            #pragma unroll
            for (int j = 0; j < 4; j++) {
                af[j][0] = pack_h2(s[2 * j][0],     s[2 * j][1]);
                af[j][1] = pack_h2(s[2 * j][2],     s[2 * j][3]);
                af[j][2] = pack_h2(s[2 * j + 1][0], s[2 * j + 1][1]);
                af[j][3] = pack_h2(s[2 * j + 1][2], s[2 * j + 1][3]);
            }

            // --- O += P V  (V fragments via ldmatrix.trans) ---
            #pragma unroll
            for (int nt = 0; nt < 8; nt++) {
                #pragma unroll
                for (int jj = 0; jj < 2; jj++) {
                    // matrices: c blocks [32jj+8*lmat, +8), cols h [8nt, +8)
                    uint32_t addr = sb + 2 * (VS_OFF
                                              + (32 * jj + 8 * lmat + lrow) * ASTR
                                              + 8 * nt);
                    unsigned r0, r1, r2, r3;
                    LDM_X4_T(r0, r1, r2, r3, addr);
                    MMA_F16(o[nt], af[2 * jj],     r0, r1);
                    MMA_F16(o[nt], af[2 * jj + 1], r2, r3);
                }
            }
        }
        __syncthreads();
    }

    // --- epilogue ---
    float inv0 = 1.0f / l0, inv1 = 1.0f / l1;
    float* op0 = out + ((size_t)b * T_ + q0 + lr) * 64;
    float* op1 = out + ((size_t)b * T_ + q0 + lr + 8) * 64;
    #pragma unroll
    for (int nt = 0; nt < 8; nt++) {
        int col = nt * 8 + 2 * t;
        *(float2*)&op0[col] = make_float2(o[nt][0] * inv0, o[nt][1] * inv0);
        *(float2*)&op1[col] = make_float2(o[nt][2] * inv1, o[nt][3] * inv1);
    }
}

// ---------------------------------------------------------------------------
extern "C" void kernel_launch(void* const* d_in, const int* in_sizes, int n_in,
                              void* d_out, int out_size)
{
    const float* x  = (const float*)d_in[0];
    const float* Wq = (const float*)d_in[1];
    const float* Wk = (const float*)d_in[2];
    const float* Wv = (const float*)d_in[3];
    float* out = (float*)d_out;

    wt_kernel<<<288, 256>>>(Wq, Wk, Wv);

    cudaFuncSetAttribute(qkv_tc2_kernel,
                         cudaFuncAttributeMaxDynamicSharedMemorySize,
                         QKV_SMEM_BYTES);
    qkv_tc2_kernel<<<M_ / 128, 512, QKV_SMEM_BYTES>>>(x);

    cudaFuncSetAttribute(attn_fp16_kernel,
                         cudaFuncAttributeMaxDynamicSharedMemorySize,
                         ATTN_SMEM_BYTES);
    attn_fp16_kernel<<<dim3(T_ / 128, B_), 256, ATTN_SMEM_BYTES>>>(out);
}

// round 9
// speedup vs baseline: 2.0086x; 1.3153x over previous
#include <cuda_runtime.h>
#include <cuda_fp16.h>
#include <math.h>
#include <stdint.h>

#define B_ 512
#define T_ 256
#define E_ 384
#define H_ 64
#define M_ (B_ * T_)   // 131072

// Projected q,k,v stored as fp16
__device__ __half g_q[(size_t)M_ * H_];
__device__ __half g_k[(size_t)M_ * H_];
__device__ __half g_v[(size_t)M_ * H_];
__device__ __half g_wh[192 * 384];   // W^T fp16: [n][k], n = m*64+h

__device__ __forceinline__ unsigned pack_h2(float lo, float hi) {
    unsigned d;
    asm("cvt.rn.f16x2.f32 %0, %1, %2;" : "=r"(d) : "f"(hi), "f"(lo));
    return d;
}
__device__ __forceinline__ uint32_t s2u(const void* p) {
    uint32_t a;
    asm("{ .reg .u64 t; cvta.to.shared.u64 t, %1; cvt.u32.u64 %0, t; }"
        : "=r"(a) : "l"(p));
    return a;
}
__device__ __forceinline__ void cpa16(uint32_t dst, const void* src) {
    asm volatile("cp.async.cg.shared.global [%0], [%1], 16;"
                 :: "r"(dst), "l"(src) : "memory");
}

#define MMA_F16(C, A, B0, B1)                                               \
    asm volatile(                                                           \
        "mma.sync.aligned.m16n8k16.row.col.f32.f16.f16.f32 "                \
        "{%0,%1,%2,%3}, {%4,%5,%6,%7}, {%8,%9}, {%0,%1,%2,%3};"             \
        : "+f"((C)[0]), "+f"((C)[1]), "+f"((C)[2]), "+f"((C)[3])            \
        : "r"((A)[0]), "r"((A)[1]), "r"((A)[2]), "r"((A)[3]),               \
          "r"(B0), "r"(B1))

#define LDM_X4(R0, R1, R2, R3, ADDR)                                        \
    asm volatile("ldmatrix.sync.aligned.m8n8.x4.shared.b16 "                \
                 "{%0,%1,%2,%3}, [%4];"                                     \
                 : "=r"(R0), "=r"(R1), "=r"(R2), "=r"(R3) : "r"(ADDR))

#define LDM_X4_T(R0, R1, R2, R3, ADDR)                                      \
    asm volatile("ldmatrix.sync.aligned.m8n8.x4.trans.shared.b16 "          \
                 "{%0,%1,%2,%3}, [%4];"                                     \
                 : "=r"(R0), "=r"(R1), "=r"(R2), "=r"(R3) : "r"(ADDR))

// ---------------------------------------------------------------------------
// Kernel 0: W -> fp16, layout g_wh[n][k]  (n = m*64 + h)
// ---------------------------------------------------------------------------
__global__ __launch_bounds__(256) void wh_kernel(
    const float* __restrict__ Wq, const float* __restrict__ Wk,
    const float* __restrict__ Wv)
{
    int idx = blockIdx.x * 256 + threadIdx.x;   // 0..73727
    int n = idx / 384, k = idx % 384;
    const float* Wm = (n < 64) ? Wq : ((n < 128) ? Wk : Wv);
    g_wh[idx] = __float2half_rn(Wm[(size_t)k * 64 + (n & 63)]);
}

// ---------------------------------------------------------------------------
// Kernel 1: fused QKV projection, fp16 mma m16n8k16 + ldmatrix.
// CTA 128 rows x 192 cols, 512 threads, 16 warps, warp tile 32x48.
// X: register-prefetch LDG -> pack fp16 -> Xh[128][40] (single buffer).
// W: cp.async double buffer Wh[2][192][40] from g_wh.
// ---------------------------------------------------------------------------
#define XH_STRIDE 40
#define WH_STRIDE 40
#define XH_HALFS  (128 * XH_STRIDE)          // 5120
#define WH_HALFS  (192 * WH_STRIDE)          // 7680 per stage
#define WH_OFF    XH_HALFS
#define QKV_SMEM_BYTES ((XH_HALFS + 2 * WH_HALFS) * 2)   // 40960

__global__ __launch_bounds__(512, 1) void qkv_fp16_kernel(const float* __restrict__ x)
{
    extern __shared__ __align__(16) __half smq[];
    const uint32_t sb = s2u(smq);
    __half* Xh = smq;

    const int tid  = threadIdx.x;
    const int warp = tid >> 5;
    const int lane = tid & 31;
    const int lrow = lane & 7;
    const int row0 = blockIdx.x * 128;

    const int mbase = (warp >> 2) * 32;   // 0,32,64,96
    const int nbase = (warp & 3) * 48;    // 0,48,96,144

    const float* xp = x + (size_t)row0 * E_;

    // per-thread X slice: row xr, 8 floats at col xc8
    const int xr  = tid >> 2;
    const int xc8 = (tid & 3) * 8;

    // W prefetch (stage s <- chunk kb)
    auto prefetchW = [&](int s, int kb) {
        const uint32_t wb = sb + (WH_OFF + s * WH_HALFS) * 2;
        #pragma unroll
        for (int i = 0; i < 2; i++) {
            int f = tid + i * 512;
            if (f < 768) {
                int n = f >> 2, cc = f & 3;
                cpa16(wb + (n * WH_STRIDE + cc * 8) * 2,
                      g_wh + (size_t)n * 384 + kb * 32 + cc * 8);
            }
        }
        asm volatile("cp.async.commit_group;" ::: "memory");
    };

    // X prefetch into registers
    float4 xa, xb, xa2, xb2;
    {
        const float* src = xp + (size_t)xr * E_ + xc8;
        xa = *(const float4*)src;
        xb = *(const float4*)(src + 4);
    }
    prefetchW(0, 0);

    float c[2][6][4] = {};

    for (int kb = 0; kb < 12; kb++) {
        const int s = kb & 1;
        if (kb + 1 < 12) {
            const float* src = xp + (size_t)xr * E_ + (kb + 1) * 32 + xc8;
            xa2 = *(const float4*)src;
            xb2 = *(const float4*)(src + 4);
            prefetchW(s ^ 1, kb + 1);
            asm volatile("cp.async.wait_group 1;" ::: "memory");
        } else {
            asm volatile("cp.async.wait_group 0;" ::: "memory");
        }

        // convert current X registers -> Xh
        {
            uint4 p;
            p.x = pack_h2(xa.x, xa.y);
            p.y = pack_h2(xa.z, xa.w);
            p.z = pack_h2(xb.x, xb.y);
            p.w = pack_h2(xb.z, xb.w);
            *(uint4*)(Xh + xr * XH_STRIDE + xc8) = p;
        }
        __syncthreads();

        const uint32_t xbse = sb;
        const uint32_t wbse = sb + (WH_OFF + s * WH_HALFS) * 2;

        #pragma unroll
        for (int kc = 0; kc < 2; kc++) {
            const int kk = kc * 16;
            unsigned a[2][4];
            #pragma unroll
            for (int mt = 0; mt < 2; mt++) {
                uint32_t addr = xbse + 2 * ((mbase + mt * 16 + ((lane >> 3) & 1) * 8
                                             + lrow) * XH_STRIDE
                                            + kk + (lane >> 4) * 8);
                LDM_X4(a[mt][0], a[mt][1], a[mt][2], a[mt][3], addr);
            }
            #pragma unroll
            for (int ntp = 0; ntp < 3; ntp++) {
                unsigned b0, b1, b2, b3;
                uint32_t addr = wbse + 2 * ((nbase + ntp * 16 + (lane >> 4) * 8
                                             + lrow) * WH_STRIDE
                                            + kk + ((lane >> 3) & 1) * 8);
                LDM_X4(b0, b1, b2, b3, addr);
                MMA_F16(c[0][2 * ntp],     a[0], b0, b1);
                MMA_F16(c[1][2 * ntp],     a[1], b0, b1);
                MMA_F16(c[0][2 * ntp + 1], a[0], b2, b3);
                MMA_F16(c[1][2 * ntp + 1], a[1], b2, b3);
            }
        }
        __syncthreads();

        xa = xa2; xb = xb2;
    }

    // Epilogue: pack fp32 accum -> fp16
    const int g = lane >> 2;
    const int t = lane & 3;
    #pragma unroll
    for (int mt = 0; mt < 2; mt++) {
        #pragma unroll
        for (int nt = 0; nt < 6; nt++) {
            int col = nbase + nt * 8 + 2 * t;
            int m = col >> 6;
            int h = col & 63;
            __half* o = (m == 0) ? g_q : ((m == 1) ? g_k : g_v);
            int r = row0 + mbase + mt * 16 + g;
            *(unsigned*)&o[(size_t)r * H_ + h]       = pack_h2(c[mt][nt][0], c[mt][nt][1]);
            *(unsigned*)&o[(size_t)(r + 8) * H_ + h] = pack_h2(c[mt][nt][2], c[mt][nt][3]);
        }
    }
}

// ---------------------------------------------------------------------------
// Kernel 2: flash attention, fp16 mma + ldmatrix (unchanged from R8, ~43us).
// ---------------------------------------------------------------------------
#define ASTR   72
#define KS_OFF 0
#define VS_OFF (64 * ASTR)
#define QS_OFF (128 * ASTR)
#define ATTN_SMEM_BYTES ((256 * ASTR) * 2)   // 36864

__global__ __launch_bounds__(256, 2) void attn_fp16_kernel(float* __restrict__ out)
{
    extern __shared__ __align__(16) __half smh[];
    const uint32_t sb = s2u(smh);
    __half* Ks = smh + KS_OFF;
    __half* Vs = smh + VS_OFF;
    __half* Qs = smh + QS_OFF;
    unsigned* Qu = (unsigned*)Qs;

    const int tid  = threadIdx.x;
    const int warp = tid >> 5;
    const int lane = tid & 31;
    const int g    = lane >> 2;
    const int t    = lane & 3;
    const int q0   = blockIdx.x * 128;
    const int b    = blockIdx.y;

    const __half* qp = g_q + ((size_t)b * T_ + q0) * H_;
    const __half2 sc = __float2half2_rn(0.125f);
    #pragma unroll
    for (int i = 0; i < 4; i++) {
        int f = tid + i * 256;
        int r = f >> 3, h8 = (f & 7) * 8;
        uint4 v = *(const uint4*)(qp + (size_t)r * 64 + h8);
        __half2* hv = (__half2*)&v;
        hv[0] = __hmul2(hv[0], sc); hv[1] = __hmul2(hv[1], sc);
        hv[2] = __hmul2(hv[2], sc); hv[3] = __hmul2(hv[3], sc);
        *(uint4*)(Qs + r * ASTR + h8) = v;
    }
    __syncthreads();

    const int lr = warp * 16 + g;
    unsigned qf[4][4];
    #pragma unroll
    for (int s = 0; s < 4; s++) {
        qf[s][0] = Qu[lr * 36 + 8 * s + t];
        qf[s][1] = Qu[(lr + 8) * 36 + 8 * s + t];
        qf[s][2] = Qu[lr * 36 + 8 * s + t + 4];
        qf[s][3] = Qu[(lr + 8) * 36 + 8 * s + t + 4];
    }

    float o[8][4] = {};
    float m0 = -1e30f, m1 = -1e30f, l0 = 0.0f, l1 = 0.0f;

    const int row_min = q0 + warp * 16;
    const int row_max = row_min + 15;
    const int r0g = row_min + g;
    const int ktmax = (q0 + 127) >> 6;

    const __half* kp = g_k + (size_t)b * T_ * H_;
    const __half* vp = g_v + (size_t)b * T_ * H_;

    const int lrow = lane & 7;
    const int lmat = lane >> 3;

    for (int kt = 0; kt <= ktmax; kt++) {
        #pragma unroll
        for (int i = 0; i < 2; i++) {
            int f = tid + i * 256;
            int c = f >> 3, h8 = (f & 7) * 8;
            *(uint4*)(Ks + c * ASTR + h8) =
                *(const uint4*)(kp + (size_t)(kt * 64 + c) * 64 + h8);
            *(uint4*)(Vs + c * ASTR + h8) =
                *(const uint4*)(vp + (size_t)(kt * 64 + c) * 64 + h8);
        }
        __syncthreads();

        if (kt * 64 <= row_max) {
            float s[8][4] = {};
            #pragma unroll
            for (int nt = 0; nt < 8; nt++) {
                #pragma unroll
                for (int jj = 0; jj < 2; jj++) {
                    uint32_t addr = sb + 2 * (KS_OFF + (nt * 8 + lrow) * ASTR
                                              + 32 * jj + 8 * lmat);
                    unsigned r0, r1, r2, r3;
                    LDM_X4(r0, r1, r2, r3, addr);
                    MMA_F16(s[nt], qf[2 * jj],     r0, r1);
                    MMA_F16(s[nt], qf[2 * jj + 1], r2, r3);
                }
            }

            if (kt * 64 + 63 > row_min) {
                int colb = kt * 64 + 2 * t;
                #pragma unroll
                for (int nt = 0; nt < 8; nt++) {
                    int c0 = colb + nt * 8, c1 = c0 + 1;
                    if (c0 > r0g)     s[nt][0] = -1e30f;
                    if (c1 > r0g)     s[nt][1] = -1e30f;
                    if (c0 > r0g + 8) s[nt][2] = -1e30f;
                    if (c1 > r0g + 8) s[nt][3] = -1e30f;
                }
            }

            float mx0 = -1e30f, mx1 = -1e30f;
            #pragma unroll
            for (int nt = 0; nt < 8; nt++) {
                mx0 = fmaxf(mx0, fmaxf(s[nt][0], s[nt][1]));
                mx1 = fmaxf(mx1, fmaxf(s[nt][2], s[nt][3]));
            }
            mx0 = fmaxf(mx0, __shfl_xor_sync(0xffffffffu, mx0, 1));
            mx0 = fmaxf(mx0, __shfl_xor_sync(0xffffffffu, mx0, 2));
            mx1 = fmaxf(mx1, __shfl_xor_sync(0xffffffffu, mx1, 1));
            mx1 = fmaxf(mx1, __shfl_xor_sync(0xffffffffu, mx1, 2));

            float mn0 = fmaxf(m0, mx0), mn1 = fmaxf(m1, mx1);
            float cr0 = __expf(m0 - mn0), cr1 = __expf(m1 - mn1);
            float sum0 = 0.0f, sum1 = 0.0f;
            #pragma unroll
            for (int nt = 0; nt < 8; nt++) {
                s[nt][0] = __expf(s[nt][0] - mn0);
                s[nt][1] = __expf(s[nt][1] - mn0);
                s[nt][2] = __expf(s[nt][2] - mn1);
                s[nt][3] = __expf(s[nt][3] - mn1);
                sum0 += s[nt][0] + s[nt][1];
                sum1 += s[nt][2] + s[nt][3];
            }
            sum0 += __shfl_xor_sync(0xffffffffu, sum0, 1);
            sum0 += __shfl_xor_sync(0xffffffffu, sum0, 2);
            sum1 += __shfl_xor_sync(0xffffffffu, sum1, 1);
            sum1 += __shfl_xor_sync(0xffffffffu, sum1, 2);

            l0 = l0 * cr0 + sum0;  l1 = l1 * cr1 + sum1;
            m0 = mn0;              m1 = mn1;
            #pragma unroll
            for (int nt = 0; nt < 8; nt++) {
                o[nt][0] *= cr0; o[nt][1] *= cr0;
                o[nt][2] *= cr1; o[nt][3] *= cr1;
            }

            unsigned af[4][4];
            #pragma unroll
            for (int j = 0; j < 4; j++) {
                af[j][0] = pack_h2(s[2 * j][0],     s[2 * j][1]);
                af[j][1] = pack_h2(s[2 * j][2],     s[2 * j][3]);
                af[j][2] = pack_h2(s[2 * j + 1][0], s[2 * j + 1][1]);
                af[j][3] = pack_h2(s[2 * j + 1][2], s[2 * j + 1][3]);
            }

            #pragma unroll
            for (int nt = 0; nt < 8; nt++) {
                #pragma unroll
                for (int jj = 0; jj < 2; jj++) {
                    uint32_t addr = sb + 2 * (VS_OFF
                                              + (32 * jj + 8 * lmat + lrow) * ASTR
                                              + 8 * nt);
                    unsigned r0, r1, r2, r3;
                    LDM_X4_T(r0, r1, r2, r3, addr);
                    MMA_F16(o[nt], af[2 * jj],     r0, r1);
                    MMA_F16(o[nt], af[2 * jj + 1], r2, r3);
                }
            }
        }
        __syncthreads();
    }

    float inv0 = 1.0f / l0, inv1 = 1.0f / l1;
    float* op0 = out + ((size_t)b * T_ + q0 + lr) * 64;
    float* op1 = out + ((size_t)b * T_ + q0 + lr + 8) * 64;
    #pragma unroll
    for (int nt = 0; nt < 8; nt++) {
        int col = nt * 8 + 2 * t;
        *(float2*)&op0[col] = make_float2(o[nt][0] * inv0, o[nt][1] * inv0);
        *(float2*)&op1[col] = make_float2(o[nt][2] * inv1, o[nt][3] * inv1);
    }
}

// ---------------------------------------------------------------------------
extern "C" void kernel_launch(void* const* d_in, const int* in_sizes, int n_in,
                              void* d_out, int out_size)
{
    const float* x  = (const float*)d_in[0];
    const float* Wq = (const float*)d_in[1];
    const float* Wk = (const float*)d_in[2];
    const float* Wv = (const float*)d_in[3];
    float* out = (float*)d_out;

    wh_kernel<<<288, 256>>>(Wq, Wk, Wv);

    cudaFuncSetAttribute(qkv_fp16_kernel,
                         cudaFuncAttributeMaxDynamicSharedMemorySize,
                         QKV_SMEM_BYTES);
    qkv_fp16_kernel<<<M_ / 128, 512, QKV_SMEM_BYTES>>>(x);

    cudaFuncSetAttribute(attn_fp16_kernel,
                         cudaFuncAttributeMaxDynamicSharedMemorySize,
                         ATTN_SMEM_BYTES);
    attn_fp16_kernel<<<dim3(T_ / 128, B_), 256, ATTN_SMEM_BYTES>>>(out);
}

// round 10
// speedup vs baseline: 2.0478x; 1.0195x over previous
#include <cuda_runtime.h>
#include <cuda_fp16.h>
#include <math.h>
#include <stdint.h>

#define B_ 512
#define T_ 256
#define E_ 384
#define H_ 64

__device__ __half g_wh[192 * 384];   // W^T fp16: [n][k], n = m*64+h

__device__ __forceinline__ unsigned pack_h2(float lo, float hi) {
    unsigned d;
    asm("cvt.rn.f16x2.f32 %0, %1, %2;" : "=r"(d) : "f"(hi), "f"(lo));
    return d;
}
__device__ __forceinline__ uint32_t s2u(const void* p) {
    uint32_t a;
    asm("{ .reg .u64 t; cvta.to.shared.u64 t, %1; cvt.u32.u64 %0, t; }"
        : "=r"(a) : "l"(p));
    return a;
}
__device__ __forceinline__ void cpa16(uint32_t dst, const void* src) {
    asm volatile("cp.async.cg.shared.global [%0], [%1], 16;"
                 :: "r"(dst), "l"(src) : "memory");
}

#define MMA_F16(C, A, B0, B1)                                               \
    asm volatile(                                                           \
        "mma.sync.aligned.m16n8k16.row.col.f32.f16.f16.f32 "                \
        "{%0,%1,%2,%3}, {%4,%5,%6,%7}, {%8,%9}, {%0,%1,%2,%3};"             \
        : "+f"((C)[0]), "+f"((C)[1]), "+f"((C)[2]), "+f"((C)[3])            \
        : "r"((A)[0]), "r"((A)[1]), "r"((A)[2]), "r"((A)[3]),               \
          "r"(B0), "r"(B1))

#define LDM_X4(R0, R1, R2, R3, ADDR)                                        \
    asm volatile("ldmatrix.sync.aligned.m8n8.x4.shared.b16 "                \
                 "{%0,%1,%2,%3}, [%4];"                                     \
                 : "=r"(R0), "=r"(R1), "=r"(R2), "=r"(R3) : "r"(ADDR))

#define LDM_X4_T(R0, R1, R2, R3, ADDR)                                      \
    asm volatile("ldmatrix.sync.aligned.m8n8.x4.trans.shared.b16 "          \
                 "{%0,%1,%2,%3}, [%4];"                                     \
                 : "=r"(R0), "=r"(R1), "=r"(R2), "=r"(R3) : "r"(ADDR))

// ---------------------------------------------------------------------------
// Kernel 0: W -> fp16, layout g_wh[n][k]  (n = m*64 + h)
// ---------------------------------------------------------------------------
__global__ __launch_bounds__(256) void wh_kernel(
    const float* __restrict__ Wq, const float* __restrict__ Wk,
    const float* __restrict__ Wv)
{
    int idx = blockIdx.x * 256 + threadIdx.x;
    int n = idx / 384, k = idx % 384;
    const float* Wm = (n < 64) ? Wq : ((n < 128) ? Wk : Wv);
    g_wh[idx] = __float2half_rn(Wm[(size_t)k * 64 + (n & 63)]);
}

// ---------------------------------------------------------------------------
// Fused kernel: one CTA per batch. 512 threads, 16 warps.
// Phase 1: project q,k,v (two 128-row sub-phases) into smem Qh/Kh/Vh.
// Phase 2: flash attention entirely from smem (no syncthreads).
//
// smem half layout:
//   Qh[256][72] | Kh[256][72] | Vh[256][72] | Xst[2][128][40] | Wst[2][192][40]
// ---------------------------------------------------------------------------
#define QSTR 72
#define QH_OFF   0
#define KH_OFF   (256 * QSTR)          // 18432
#define VH_OFF   (512 * QSTR)          // 36864
#define XST_OFF  (768 * QSTR)          // 55296
#define XST_SZ   (128 * 40)            // 5120 per stage
#define WST_OFF  (XST_OFF + 2 * XST_SZ) // 65536
#define WST_SZ   (192 * 40)            // 7680 per stage
#define SMEM_HALFS (WST_OFF + 2 * WST_SZ)   // 80896
#define FUSED_SMEM_BYTES (SMEM_HALFS * 2)   // 161792

__global__ __launch_bounds__(512, 1) void fused_attn_kernel(
    const float* __restrict__ x, float* __restrict__ out)
{
    extern __shared__ __align__(16) __half smh[];
    const uint32_t sb = s2u(smh);
    __half* Qh = smh + QH_OFF;
    __half* Kh = smh + KH_OFF;
    __half* Vh = smh + VH_OFF;
    __half* Xst = smh + XST_OFF;

    const int tid  = threadIdx.x;
    const int warp = tid >> 5;
    const int lane = tid & 31;
    const int g    = lane >> 2;
    const int t    = lane & 3;
    const int lrow = lane & 7;
    const int lmat = lane >> 3;
    const int b    = blockIdx.x;

    const int mbase = (warp >> 2) * 32;   // 0,32,64,96
    const int nbase = (warp & 3) * 48;    // 0,48,96,144

    const int xr  = tid >> 2;             // 0..127
    const int xc8 = (tid & 3) * 8;

    // ---- helpers ----
    auto prefetchW = [&](int s, int kb) {
        const uint32_t wb = sb + (WST_OFF + s * WST_SZ) * 2;
        #pragma unroll
        for (int i = 0; i < 2; i++) {
            int f = tid + i * 512;
            if (f < 768) {
                int n = f >> 2, cc = f & 3;
                cpa16(wb + (n * 40 + cc * 8) * 2,
                      g_wh + (size_t)n * 384 + kb * 32 + cc * 8);
            }
        }
        asm volatile("cp.async.commit_group;" ::: "memory");
    };
    auto stsX = [&](int s, const float4& a, const float4& bq) {
        uint4 p;
        p.x = pack_h2(a.x, a.y);
        p.y = pack_h2(a.z, a.w);
        p.z = pack_h2(bq.x, bq.y);
        p.w = pack_h2(bq.z, bq.w);
        *(uint4*)(Xst + s * XST_SZ + xr * 40 + xc8) = p;
    };

    // =========================== Phase 1: QKV ===========================
    #pragma unroll 1
    for (int sp = 0; sp < 2; sp++) {
        const float* xp = x + ((size_t)b * 256 + sp * 128) * E_;

        float4 xa, xb, xa2, xb2;
        {
            const float* src = xp + (size_t)xr * E_ + xc8;
            xa = *(const float4*)src;
            xb = *(const float4*)(src + 4);
        }
        prefetchW(0, 0);
        stsX(0, xa, xb);
        __syncthreads();

        float c[2][6][4] = {};

        #pragma unroll 1
        for (int kb = 0; kb < 12; kb++) {
            const int s = kb & 1;
            if (kb + 1 < 12) {
                const float* src = xp + (size_t)xr * E_ + (kb + 1) * 32 + xc8;
                xa2 = *(const float4*)src;
                xb2 = *(const float4*)(src + 4);
                prefetchW(s ^ 1, kb + 1);
                asm volatile("cp.async.wait_group 1;" ::: "memory");
            } else {
                asm volatile("cp.async.wait_group 0;" ::: "memory");
            }

            const uint32_t xbse = sb + (XST_OFF + s * XST_SZ) * 2;
            const uint32_t wbse = sb + (WST_OFF + s * WST_SZ) * 2;

            #pragma unroll
            for (int kc = 0; kc < 2; kc++) {
                const int kk = kc * 16;
                unsigned a[2][4];
                #pragma unroll
                for (int mt = 0; mt < 2; mt++) {
                    uint32_t addr = xbse + 2 * ((mbase + mt * 16
                                                 + ((lane >> 3) & 1) * 8
                                                 + lrow) * 40
                                                + kk + (lane >> 4) * 8);
                    LDM_X4(a[mt][0], a[mt][1], a[mt][2], a[mt][3], addr);
                }
                #pragma unroll
                for (int ntp = 0; ntp < 3; ntp++) {
                    unsigned b0, b1, b2, b3;
                    uint32_t addr = wbse + 2 * ((nbase + ntp * 16
                                                 + (lane >> 4) * 8
                                                 + lrow) * 40
                                                + kk + ((lane >> 3) & 1) * 8);
                    LDM_X4(b0, b1, b2, b3, addr);
                    MMA_F16(c[0][2 * ntp],     a[0], b0, b1);
                    MMA_F16(c[1][2 * ntp],     a[1], b0, b1);
                    MMA_F16(c[0][2 * ntp + 1], a[0], b2, b3);
                    MMA_F16(c[1][2 * ntp + 1], a[1], b2, b3);
                }
            }

            if (kb + 1 < 12) stsX(s ^ 1, xa2, xb2);
            __syncthreads();
        }

        // epilogue -> smem (Q scaled by 1/sqrt(d))
        #pragma unroll
        for (int mt = 0; mt < 2; mt++) {
            #pragma unroll
            for (int nt = 0; nt < 6; nt++) {
                int col = nbase + nt * 8 + 2 * t;
                int m = col >> 6;
                int h = col & 63;
                __half* dst = (m == 0) ? Qh : ((m == 1) ? Kh : Vh);
                float scl = (m == 0) ? 0.125f : 1.0f;
                int r = sp * 128 + mbase + mt * 16 + g;
                *(unsigned*)&dst[r * QSTR + h] =
                    pack_h2(c[mt][nt][0] * scl, c[mt][nt][1] * scl);
                *(unsigned*)&dst[(r + 8) * QSTR + h] =
                    pack_h2(c[mt][nt][2] * scl, c[mt][nt][3] * scl);
            }
        }
    }
    __syncthreads();

    // ========================= Phase 2: attention =========================
    // warp w owns q rows [w*16, w*16+16); K/V resident in smem.
    const int row_min = warp * 16;
    const int r0g = row_min + g;
    const int ktw = (row_min + 15) >> 6;

    unsigned qf[4][4];
    #pragma unroll
    for (int ks = 0; ks < 4; ks++) {
        uint32_t addr = sb + 2 * (QH_OFF + (row_min + ((lane >> 3) & 1) * 8
                                            + lrow) * QSTR
                                  + ks * 16 + (lane >> 4) * 8);
        LDM_X4(qf[ks][0], qf[ks][1], qf[ks][2], qf[ks][3], addr);
    }

    float o[8][4] = {};
    float m0 = -1e30f, m1 = -1e30f, l0 = 0.0f, l1 = 0.0f;

    #pragma unroll 1
    for (int kt = 0; kt <= ktw; kt++) {
        // --- S = Q K^T ---
        float s[8][4] = {};
        #pragma unroll
        for (int nt = 0; nt < 8; nt++) {
            #pragma unroll
            for (int jj = 0; jj < 2; jj++) {
                uint32_t addr = sb + 2 * (KH_OFF + (kt * 64 + nt * 8 + lrow) * QSTR
                                          + 32 * jj + 8 * lmat);
                unsigned r0, r1, r2, r3;
                LDM_X4(r0, r1, r2, r3, addr);
                MMA_F16(s[nt], qf[2 * jj],     r0, r1);
                MMA_F16(s[nt], qf[2 * jj + 1], r2, r3);
            }
        }

        // --- causal mask ---
        if (kt * 64 + 63 > row_min) {
            int colb = kt * 64 + 2 * t;
            #pragma unroll
            for (int nt = 0; nt < 8; nt++) {
                int c0 = colb + nt * 8, c1 = c0 + 1;
                if (c0 > r0g)     s[nt][0] = -1e30f;
                if (c1 > r0g)     s[nt][1] = -1e30f;
                if (c0 > r0g + 8) s[nt][2] = -1e30f;
                if (c1 > r0g + 8) s[nt][3] = -1e30f;
            }
        }

        // --- online softmax (rows r0g, r0g+8) ---
        float mx0 = -1e30f, mx1 = -1e30f;
        #pragma unroll
        for (int nt = 0; nt < 8; nt++) {
            mx0 = fmaxf(mx0, fmaxf(s[nt][0], s[nt][1]));
            mx1 = fmaxf(mx1, fmaxf(s[nt][2], s[nt][3]));
        }
        mx0 = fmaxf(mx0, __shfl_xor_sync(0xffffffffu, mx0, 1));
        mx0 = fmaxf(mx0, __shfl_xor_sync(0xffffffffu, mx0, 2));
        mx1 = fmaxf(mx1, __shfl_xor_sync(0xffffffffu, mx1, 1));
        mx1 = fmaxf(mx1, __shfl_xor_sync(0xffffffffu, mx1, 2));

        float mn0 = fmaxf(m0, mx0), mn1 = fmaxf(m1, mx1);
        float cr0 = __expf(m0 - mn0), cr1 = __expf(m1 - mn1);
        float sum0 = 0.0f, sum1 = 0.0f;
        #pragma unroll
        for (int nt = 0; nt < 8; nt++) {
            s[nt][0] = __expf(s[nt][0] - mn0);
            s[nt][1] = __expf(s[nt][1] - mn0);
            s[nt][2] = __expf(s[nt][2] - mn1);
            s[nt][3] = __expf(s[nt][3] - mn1);
            sum0 += s[nt][0] + s[nt][1];
            sum1 += s[nt][2] + s[nt][3];
        }
        sum0 += __shfl_xor_sync(0xffffffffu, sum0, 1);
        sum0 += __shfl_xor_sync(0xffffffffu, sum0, 2);
        sum1 += __shfl_xor_sync(0xffffffffu, sum1, 1);
        sum1 += __shfl_xor_sync(0xffffffffu, sum1, 2);

        l0 = l0 * cr0 + sum0;  l1 = l1 * cr1 + sum1;
        m0 = mn0;              m1 = mn1;
        #pragma unroll
        for (int nt = 0; nt < 8; nt++) {
            o[nt][0] *= cr0; o[nt][1] *= cr0;
            o[nt][2] *= cr1; o[nt][3] *= cr1;
        }

        // --- P repack in registers ---
        unsigned af[4][4];
        #pragma unroll
        for (int j = 0; j < 4; j++) {
            af[j][0] = pack_h2(s[2 * j][0],     s[2 * j][1]);
            af[j][1] = pack_h2(s[2 * j][2],     s[2 * j][3]);
            af[j][2] = pack_h2(s[2 * j + 1][0], s[2 * j + 1][1]);
            af[j][3] = pack_h2(s[2 * j + 1][2], s[2 * j + 1][3]);
        }

        // --- O += P V ---
        #pragma unroll
        for (int nt = 0; nt < 8; nt++) {
            #pragma unroll
            for (int jj = 0; jj < 2; jj++) {
                uint32_t addr = sb + 2 * (VH_OFF + (kt * 64 + 32 * jj + 8 * lmat
                                                    + lrow) * QSTR
                                          + 8 * nt);
                unsigned r0, r1, r2, r3;
                LDM_X4_T(r0, r1, r2, r3, addr);
                MMA_F16(o[nt], af[2 * jj],     r0, r1);
                MMA_F16(o[nt], af[2 * jj + 1], r2, r3);
            }
        }
    }

    // --- epilogue ---
    float inv0 = 1.0f / l0, inv1 = 1.0f / l1;
    float* op0 = out + ((size_t)b * 256 + r0g) * 64;
    float* op1 = out + ((size_t)b * 256 + r0g + 8) * 64;
    #pragma unroll
    for (int nt = 0; nt < 8; nt++) {
        int col = nt * 8 + 2 * t;
        *(float2*)&op0[col] = make_float2(o[nt][0] * inv0, o[nt][1] * inv0);
        *(float2*)&op1[col] = make_float2(o[nt][2] * inv1, o[nt][3] * inv1);
    }
}

// ---------------------------------------------------------------------------
extern "C" void kernel_launch(void* const* d_in, const int* in_sizes, int n_in,
                              void* d_out, int out_size)
{
    const float* x  = (const float*)d_in[0];
    const float* Wq = (const float*)d_in[1];
    const float* Wk = (const float*)d_in[2];
    const float* Wv = (const float*)d_in[3];
    float* out = (float*)d_out;

    wh_kernel<<<288, 256>>>(Wq, Wk, Wv);

    cudaFuncSetAttribute(fused_attn_kernel,
                         cudaFuncAttributeMaxDynamicSharedMemorySize,
                         FUSED_SMEM_BYTES);
    fused_attn_kernel<<<B_, 512, FUSED_SMEM_BYTES>>>(x, out);
}